// round 16
// baseline (speedup 1.0000x reference)
#include <cuda_runtime.h>
#include <cuda_fp16.h>
#include <cstdint>

// Problem constants
#define BATCH 2
#define SEQ   2048
#define DMODEL 1024
#define NHEAD 16
#define HDIM  64
#define ROWS  (BATCH*SEQ)          // 4096
#define ELEMS (ROWS*DMODEL)        // 4,194,304
#define KEFF  1024                 // hi-only fp16, K = DMODEL

// Scratch (static __device__ globals — allocation-free per harness rules)
__device__ float g_m[BATCH*NHEAD*HDIM*HDIM];   // 131072 floats
__device__ float g_bias_ctx[BATCH*DMODEL];
__device__ __half g_kh[(size_t)NHEAD*ROWS*64];     // K'_hi (masked)    8MB
__device__ __half g_vh[(size_t)NHEAD*ROWS*64];     // V_hi              8MB
__device__ __half g_abar[(size_t)ROWS*KEFF];       // X_hi [4096,1024]  8MB
__device__ __half g_bbar[(size_t)4*DMODEL*KEFF];   // Wk,Wv,Bctx0,Bctx1 8MB

// ---------------------------------------------------------------------------
// Base-target (sm_80+) PTX helpers: ldmatrix / mma.sync / cp.async
// ---------------------------------------------------------------------------
__device__ __forceinline__ uint32_t smem_to_u32(const void* p) {
    uint32_t a;
    asm("{ .reg .u64 t; cvta.to.shared.u64 t, %1; cvt.u32.u64 %0, t; }" : "=r"(a) : "l"(p));
    return a;
}
__device__ __forceinline__ void ldsm_x4(uint32_t& r0, uint32_t& r1, uint32_t& r2, uint32_t& r3,
                                        uint32_t addr) {
    asm volatile("ldmatrix.sync.aligned.m8n8.x4.shared.b16 {%0,%1,%2,%3}, [%4];"
                 : "=r"(r0), "=r"(r1), "=r"(r2), "=r"(r3) : "r"(addr));
}
__device__ __forceinline__ void ldsm_x4_t(uint32_t& r0, uint32_t& r1, uint32_t& r2, uint32_t& r3,
                                          uint32_t addr) {
    asm volatile("ldmatrix.sync.aligned.m8n8.x4.trans.shared.b16 {%0,%1,%2,%3}, [%4];"
                 : "=r"(r0), "=r"(r1), "=r"(r2), "=r"(r3) : "r"(addr));
}
__device__ __forceinline__ void mma_f16(float* d, uint32_t a0, uint32_t a1, uint32_t a2,
                                        uint32_t a3, uint32_t b0, uint32_t b1) {
    asm volatile("mma.sync.aligned.m16n8k16.row.col.f32.f16.f16.f32 "
                 "{%0,%1,%2,%3}, {%4,%5,%6,%7}, {%8,%9}, {%0,%1,%2,%3};"
                 : "+f"(d[0]), "+f"(d[1]), "+f"(d[2]), "+f"(d[3])
                 : "r"(a0), "r"(a1), "r"(a2), "r"(a3), "r"(b0), "r"(b1));
}
#define CP_ASYNC16(saddr, gptr) \
    asm volatile("cp.async.cg.shared.global [%0], [%1], 16;" :: "r"(saddr), "l"(gptr))
#define CP_COMMIT() asm volatile("cp.async.commit_group;" ::: "memory")
#define CP_WAIT1()  asm volatile("cp.async.wait_group 1;" ::: "memory")
#define CP_WAIT0()  asm volatile("cp.async.wait_group 0;" ::: "memory")

// SW128 swizzle: rows of 128B, chunk16B index ^= (row & 7)
#define SWZ128(bo) ((bo) ^ (((bo) >> 3) & 0x70))

// ---------------------------------------------------------------------------
// X -> X_hi (fp16). Also zeroes g_m.
// ---------------------------------------------------------------------------
__global__ __launch_bounds__(256) void conv_x(const float* __restrict__ X)
{
    if (blockIdx.x < 512) g_m[blockIdx.x * 256 + threadIdx.x] = 0.0f;

    int t = blockIdx.x * 256 + threadIdx.x;
    int idx = t * 4;
    float4 v = *(const float4*)(X + idx);
    __half* base = g_abar + idx;
    *(__half2*)(base)     = __half2(__float2half(v.x), __float2half(v.y));
    *(__half2*)(base + 2) = __half2(__float2half(v.z), __float2half(v.w));
}

// Wk,Wv -> W_hi (fp16), slabs 0,1
__global__ __launch_bounds__(256) void conv_w(const float* __restrict__ Wk,
                                              const float* __restrict__ Wv)
{
    int which = blockIdx.y;
    const float* __restrict__ W = (which == 0) ? Wk : Wv;
    int t = blockIdx.x * 256 + threadIdx.x;
    int idx = t * 4;
    float4 v = *(const float4*)(W + idx);
    __half* base = g_bbar + (size_t)which * DMODEL * KEFF + idx;
    *(__half2*)(base)     = __half2(__float2half(v.x), __float2half(v.y));
    *(__half2*)(base + 2) = __half2(__float2half(v.z), __float2half(v.w));
}

// ---------------------------------------------------------------------------
// mma.sync fp16 GEMM (hi*hi, K=1024, NIT=16), Y = Abar @ Bbar[slab]^T + bias.
// which 0: K' (mask, +bk) -> g_kh fp16; which 1: V (+bv) -> g_vh fp16;
// which >=2: ctx (slab 2+b, +bias_ctx[b]) -> out fp32.
// CTA 128x128, BK=64, 8 warps (2x4), warp tile 64x32, 2-stage cp.async,
// 2 CTAs/SM. dynamic smem = 64KB
// ---------------------------------------------------------------------------
#define BKC 64
#define NITER (KEFF / BKC)   // 16
#define CHUNK_BYTES 16384    // 128 rows * 128B
#define BUF_BYTES   32768    // A chunk + B chunk

__global__ __launch_bounds__(256, 2)
void qkv_mma(int zbase,
             const float* __restrict__ amask,
             const float* __restrict__ bk,
             const float* __restrict__ bv,
             float* __restrict__ out)
{
    extern __shared__ __align__(1024) uint8_t smem[];
    __shared__ float sBias[128];

    const int tid  = threadIdx.x;
    const int wid  = tid >> 5;
    const int lane = tid & 31;
    const int which = blockIdx.z + zbase;
    const int m0 = blockIdx.y * 128;
    const int n0 = blockIdx.x * 128;

    int slab = which;
    const float* bias;
    if (which == 0)      bias = bk;
    else if (which == 1) bias = bv;
    else {
        const int b = (m0 >= SEQ) ? 1 : 0;
        slab = 2 + b;
        bias = g_bias_ctx + b * DMODEL;
    }
    __half* __restrict__ Yh = (which == 0) ? g_kh : g_vh;

    const __half* __restrict__ Ag = g_abar;
    const __half* __restrict__ Bg = g_bbar + (size_t)slab * DMODEL * KEFF;

    const uint32_t sbase = smem_to_u32(smem);

    if (tid < 128) sBias[tid] = bias[n0 + tid];

    const int srow = tid >> 3;        // 0..31
    const int sc   = tid & 7;         // 16B chunk within 128B row

    auto stage = [&](int buf, int it) {
        const int ke = it * BKC;
        const uint32_t abase = sbase + buf * BUF_BYTES;
        const uint32_t bbase = abase + CHUNK_BYTES;
#pragma unroll
        for (int p = 0; p < 4; p++) {
            const int row = srow + p * 32;
            const uint32_t so = SWZ128((uint32_t)(row * 128 + sc * 16));
            CP_ASYNC16(abase + so, Ag + (size_t)(m0 + row) * KEFF + ke + sc * 8);
            CP_ASYNC16(bbase + so, Bg + (size_t)(n0 + row) * KEFF + ke + sc * 8);
        }
    };

    // warp tiling: 2 warps along M, 4 along N
    const int wm0 = (wid & 1) * 64;
    const int wn0 = (wid >> 1) * 32;

    float acc[16][4];
#pragma unroll
    for (int i = 0; i < 16; i++)
#pragma unroll
        for (int j = 0; j < 4; j++) acc[i][j] = 0.0f;

    const int a_row = wm0 + (lane & 15);
    const int a_ch  = (lane >> 4);
    const int b_g   = lane >> 3;
    const int b_row = wn0 + ((b_g >> 1) << 3) + (lane & 7);
    const int b_ch  = (b_g & 1);

    stage(0, 0);
    CP_COMMIT();

    for (int it = 0; it < NITER; it++) {
        if (it + 1 < NITER) {
            stage((it + 1) & 1, it + 1);
            CP_COMMIT();
            CP_WAIT1();
        } else {
            CP_WAIT0();
        }
        __syncthreads();

        const uint32_t abase = sbase + (it & 1) * BUF_BYTES;
        const uint32_t bbase = abase + CHUNK_BYTES;

#pragma unroll
        for (int ks = 0; ks < 4; ks++) {
            uint32_t a[4][4];
#pragma unroll
            for (int mi = 0; mi < 4; mi++) {
                const int row = a_row + mi * 16;
                const int ch  = ks * 2 + a_ch;
                ldsm_x4(a[mi][0], a[mi][1], a[mi][2], a[mi][3],
                        abase + SWZ128((uint32_t)(row * 128 + ch * 16)));
            }
            uint32_t b[2][4];
#pragma unroll
            for (int np = 0; np < 2; np++) {
                const int row = b_row + np * 16;
                const int ch  = ks * 2 + b_ch;
                ldsm_x4(b[np][0], b[np][1], b[np][2], b[np][3],
                        bbase + SWZ128((uint32_t)(row * 128 + ch * 16)));
            }
#pragma unroll
            for (int mi = 0; mi < 4; mi++)
#pragma unroll
                for (int ni = 0; ni < 4; ni++) {
                    const int np = ni >> 1, hf = (ni & 1) * 2;
                    mma_f16(acc[mi * 4 + ni], a[mi][0], a[mi][1], a[mi][2], a[mi][3],
                            b[np][hf], b[np][hf + 1]);
                }
        }
        __syncthreads();
    }

    // Epilogue
    const int erow = wm0 + (lane >> 2);
    const int ecol = wn0 + (lane & 3) * 2;
#pragma unroll
    for (int mi = 0; mi < 4; mi++) {
        const int r0 = m0 + erow + mi * 16;
        const int r1 = r0 + 8;
        float mv0 = 1.0f, mv1 = 1.0f;
        if (which == 0) {
            mv0 = (amask[r0] >= 0.0f) ? 1.0f : 0.0f;
            mv1 = (amask[r1] >= 0.0f) ? 1.0f : 0.0f;
        }
#pragma unroll
        for (int ni = 0; ni < 4; ni++) {
            const int c = ecol + ni * 8;
            float v00 = (acc[mi * 4 + ni][0] + sBias[c + 0]) * mv0;
            float v01 = (acc[mi * 4 + ni][1] + sBias[c + 1]) * mv0;
            float v10 = (acc[mi * 4 + ni][2] + sBias[c + 0]) * mv1;
            float v11 = (acc[mi * 4 + ni][3] + sBias[c + 1]) * mv1;
            if (which >= 2) {
                float* p0 = out + (size_t)r0 * DMODEL + n0 + c;
                float* p1 = out + (size_t)r1 * DMODEL + n0 + c;
                *(float2*)p0 = make_float2(v00, v01);
                *(float2*)p1 = make_float2(v10, v11);
            } else {
                const int gcol = n0 + c;
                const int hh = gcol >> 6, d = gcol & 63;
                __half* p0 = Yh + ((size_t)hh * ROWS + r0) * 64 + d;
                __half* p1 = Yh + ((size_t)hh * ROWS + r1) * 64 + d;
                *(__half2*)p0 = __half2(__float2half(v00), __float2half(v01));
                *(__half2*)p1 = __half2(__float2half(v10), __float2half(v11));
            }
        }
    }
}

// ---------------------------------------------------------------------------
// M[b,h] += K'[b,h]^T @ V[b,h] over a 128-key slice, tensor cores.
// grid (32 bh, 16 splits), 128 threads (4 warps: M=64, N=16 each).
// ---------------------------------------------------------------------------
__global__ __launch_bounds__(128)
void kv_mma()
{
    __shared__ __align__(1024) uint8_t sK[16384];   // 128 keys x 64 halfs
    __shared__ __align__(1024) uint8_t sV[16384];

    const int tid  = threadIdx.x;
    const int wid  = tid >> 5;
    const int lane = tid & 31;
    const int bh = blockIdx.x;
    const int b = bh >> 4, h = bh & 15;
    const int kbase = blockIdx.y * 128;

    const uint32_t sKb = smem_to_u32(sK);
    const uint32_t sVb = smem_to_u32(sV);

    {
        const size_t grow = ((size_t)h * ROWS + b * SEQ + kbase + tid) * 64;
#pragma unroll
        for (int c = 0; c < 8; c++) {
            const uint32_t so = SWZ128((uint32_t)(tid * 128 + c * 16));
            CP_ASYNC16(sKb + so, g_kh + grow + c * 8);
            CP_ASYNC16(sVb + so, g_vh + grow + c * 8);
        }
        CP_COMMIT();
    }
    CP_WAIT0();
    __syncthreads();

    const int wn0 = wid * 16;

    float acc[4][2][4];
#pragma unroll
    for (int i = 0; i < 4; i++)
#pragma unroll
        for (int j = 0; j < 2; j++)
#pragma unroll
            for (int k = 0; k < 4; k++) acc[i][j][k] = 0.0f;

    const int ka_key = (lane & 7) + ((lane >> 4) & 1) * 8;
    const int ka_dim = ((lane >> 3) & 1) * 8;
    const int kb_key = (lane & 7) + ((lane >> 3) & 1) * 8;
    const int kb_dim = wn0 + ((lane >> 4) & 1) * 8;

#pragma unroll
    for (int kk = 0; kk < 8; kk++) {
        uint32_t a[4][4];
#pragma unroll
        for (int mi = 0; mi < 4; mi++) {
            const int key = kk * 16 + ka_key;
            const int dim = mi * 16 + ka_dim;
            ldsm_x4_t(a[mi][0], a[mi][1], a[mi][2], a[mi][3],
                      sKb + SWZ128((uint32_t)(key * 128 + dim * 2)));
        }
        uint32_t bb[4];
        {
            const int key = kk * 16 + kb_key;
            ldsm_x4_t(bb[0], bb[1], bb[2], bb[3],
                      sVb + SWZ128((uint32_t)(key * 128 + kb_dim * 2)));
        }
#pragma unroll
        for (int mi = 0; mi < 4; mi++)
#pragma unroll
            for (int ni = 0; ni < 2; ni++)
                mma_f16(acc[mi][ni], a[mi][0], a[mi][1], a[mi][2], a[mi][3],
                        bb[ni * 2], bb[ni * 2 + 1]);
    }

    float* Mout = g_m + (size_t)bh * HDIM * HDIM;
    const int em = lane >> 2;
    const int en = (lane & 3) * 2;
#pragma unroll
    for (int mi = 0; mi < 4; mi++) {
        const int m = mi * 16 + em;
#pragma unroll
        for (int ni = 0; ni < 2; ni++) {
            const int n = wn0 + ni * 8 + en;
            atomicAdd(&Mout[m * HDIM + n],           acc[mi][ni][0]);
            atomicAdd(&Mout[m * HDIM + n + 1],       acc[mi][ni][1]);
            atomicAdd(&Mout[(m + 8) * HDIM + n],     acc[mi][ni][2]);
            atomicAdd(&Mout[(m + 8) * HDIM + n + 1], acc[mi][ni][3]);
        }
    }
}

// ---------------------------------------------------------------------------
// Bctx[b][n=h*64+j][k] = sum_c M[b,h][c][j] * Wq[h*64+c][k], fp16 -> slab 2+b.
// Also bias_ctx[b][h*64+j] = sum_c bq[h*64+c] * M[b,h][c][j].
// grid (16 heads, 8 kblocks, 2 batch), 256 threads.
// ---------------------------------------------------------------------------
__global__ __launch_bounds__(256)
void make_bctx(const float* __restrict__ Wq, const float* __restrict__ bq)
{
    const int h  = blockIdx.x;
    const int kb = blockIdx.y;
    const int b  = blockIdx.z;

    __shared__ float sM[64][64];    // 16KB  M[c][j]
    __shared__ float sW[64][128];   // 32KB  Wq[h*64+c][kb*128+kk]

    const int tid = threadIdx.x;

    {
        const float* Msrc = g_m + (size_t)(b * NHEAD + h) * HDIM * HDIM;
        float* Md = &sM[0][0];
#pragma unroll
        for (int i = 0; i < 4; i++) {
            int idx = tid * 16 + i * 4;
            *(float4*)(Md + idx) = *(const float4*)(Msrc + idx);
        }
    }
    {
        const int c  = tid >> 2;
        const int f0 = (tid & 3) * 8;
        const float* Wr = Wq + (size_t)(h * 64 + c) * DMODEL + kb * 128;
#pragma unroll
        for (int i = 0; i < 8; i++)
            *(float4*)(&sW[c][f0 * 4 + i * 4]) = *(const float4*)(Wr + f0 * 4 + i * 4);
    }
    __syncthreads();

    const int j  = tid >> 2;
    const int kq = tid & 3;

    float acc[32];
#pragma unroll
    for (int i = 0; i < 32; i++) acc[i] = 0.0f;

#pragma unroll 4
    for (int c = 0; c < 64; c++) {
        const float mv = sM[c][j];
        const float4* wr = (const float4*)(&sW[c][kq * 32]);
#pragma unroll
        for (int q = 0; q < 8; q++) {
            float4 w = wr[q];
            acc[q * 4 + 0] += mv * w.x;
            acc[q * 4 + 1] += mv * w.y;
            acc[q * 4 + 2] += mv * w.z;
            acc[q * 4 + 3] += mv * w.w;
        }
    }

    {
        __half* base = g_bbar + (size_t)(2 + b) * DMODEL * KEFF
                     + (size_t)(h * 64 + j) * KEFF + kb * 128 + kq * 32;
#pragma unroll
        for (int i = 0; i < 32; i += 2)
            *(__half2*)(base + i) = __half2(__float2half(acc[i]), __float2half(acc[i + 1]));
    }

    if (kb == 0 && tid < 64) {
        float s = 0.0f;
#pragma unroll 8
        for (int c = 0; c < 64; c++) s += bq[h * 64 + c] * sM[c][tid];
        g_bias_ctx[b * DMODEL + h * 64 + tid] = s;
    }
}

// ---------------------------------------------------------------------------
// Launch: conv_x/conv_w in parallel, then serial chain KV -> kv_mma ->
// make_bctx -> ctx GEMM (on capture stream).
// ---------------------------------------------------------------------------
extern "C" void kernel_launch(void* const* d_in, const int* in_sizes, int n_in,
                              void* d_out, int out_size)
{
    const float* X     = (const float*)d_in[0];
    const float* amask = (const float*)d_in[1];
    const float* Wq    = (const float*)d_in[2];
    const float* bq    = (const float*)d_in[3];
    const float* Wk    = (const float*)d_in[4];
    const float* bk    = (const float*)d_in[5];
    const float* Wv    = (const float*)d_in[6];
    const float* bv    = (const float*)d_in[7];
    float* out = (float*)d_out;

    static cudaStream_t s_kv = nullptr, s_q = nullptr;
    static cudaEvent_t ev_fork = nullptr, ev_convw = nullptr, ev_kv = nullptr;
    if (s_kv == nullptr) {
        cudaStreamCreateWithFlags(&s_kv, cudaStreamNonBlocking);
        cudaStreamCreateWithFlags(&s_q,  cudaStreamNonBlocking);
        cudaEventCreateWithFlags(&ev_fork,  cudaEventDisableTiming);
        cudaEventCreateWithFlags(&ev_convw, cudaEventDisableTiming);
        cudaEventCreateWithFlags(&ev_kv,    cudaEventDisableTiming);
        cudaFuncSetAttribute(qkv_mma, cudaFuncAttributeMaxDynamicSharedMemorySize,
                             2 * BUF_BYTES);
    }

    // fork
    cudaEventRecord(ev_fork, 0);
    cudaStreamWaitEvent(s_kv, ev_fork, 0);
    cudaStreamWaitEvent(s_q,  ev_fork, 0);

    // conversions in parallel
    conv_x<<<ELEMS / 4 / 256, 256, 0, s_kv>>>(X);                         // X_hi + zero_m
    conv_w<<<dim3(DMODEL * DMODEL / 4 / 256, 2), 256, 0, s_q>>>(Wk, Wv);
    cudaEventRecord(ev_convw, s_q);
    cudaStreamWaitEvent(s_kv, ev_convw, 0);

    // serial chain on s_kv
    qkv_mma<<<dim3(8, 32, 2), 256, 2 * BUF_BYTES, s_kv>>>(0, amask, bk, bv, out); // K,V
    kv_mma<<<dim3(BATCH * NHEAD, 16), 128, 0, s_kv>>>();
    make_bctx<<<dim3(NHEAD, 8, BATCH), 256, 0, s_kv>>>(Wq, bq);
    cudaEventRecord(ev_kv, s_kv);

    // join: ctx GEMM on capture stream
    cudaStreamWaitEvent(0, ev_kv, 0);
    qkv_mma<<<dim3(8, 32, 1), 256, 2 * BUF_BYTES>>>(2, amask, bk, bv, out);       // ctx
}

// round 17
// speedup vs baseline: 1.6080x; 1.6080x over previous
#include <cuda_runtime.h>
#include <cuda_fp16.h>
#include <cstdint>

// Problem constants
#define BATCH 2
#define SEQ   2048
#define DMODEL 1024
#define NHEAD 16
#define HDIM  64
#define ROWS  (BATCH*SEQ)          // 4096
#define ELEMS (ROWS*DMODEL)        // 4,194,304
#define KEFF  1024                 // hi-only fp16, K = DMODEL

// Scratch (static __device__ globals — allocation-free per harness rules)
__device__ float g_m[BATCH*NHEAD*HDIM*HDIM];   // 131072 floats
__device__ __half g_qs[(size_t)NHEAD*ROWS*64];     // Q_hi [h][row][64] 8MB
__device__ __half g_kh[(size_t)NHEAD*ROWS*64];     // K'_hi (masked)    8MB
__device__ __half g_vh[(size_t)NHEAD*ROWS*64];     // V_hi              8MB
__device__ __half g_abar[(size_t)ROWS*KEFF];       // X_hi [4096,1024]  8MB
__device__ __half g_bbar[(size_t)3*DMODEL*KEFF];   // W_hi 3x[1024,1024] 6MB

// ---------------------------------------------------------------------------
// Base-target (sm_80+) PTX helpers: ldmatrix / mma.sync / cp.async
// ---------------------------------------------------------------------------
__device__ __forceinline__ uint32_t smem_to_u32(const void* p) {
    uint32_t a;
    asm("{ .reg .u64 t; cvta.to.shared.u64 t, %1; cvt.u32.u64 %0, t; }" : "=r"(a) : "l"(p));
    return a;
}
__device__ __forceinline__ void ldsm_x4(uint32_t& r0, uint32_t& r1, uint32_t& r2, uint32_t& r3,
                                        uint32_t addr) {
    asm volatile("ldmatrix.sync.aligned.m8n8.x4.shared.b16 {%0,%1,%2,%3}, [%4];"
                 : "=r"(r0), "=r"(r1), "=r"(r2), "=r"(r3) : "r"(addr));
}
__device__ __forceinline__ void ldsm_x4_t(uint32_t& r0, uint32_t& r1, uint32_t& r2, uint32_t& r3,
                                          uint32_t addr) {
    asm volatile("ldmatrix.sync.aligned.m8n8.x4.trans.shared.b16 {%0,%1,%2,%3}, [%4];"
                 : "=r"(r0), "=r"(r1), "=r"(r2), "=r"(r3) : "r"(addr));
}
__device__ __forceinline__ void mma_f16(float* d, uint32_t a0, uint32_t a1, uint32_t a2,
                                        uint32_t a3, uint32_t b0, uint32_t b1) {
    asm volatile("mma.sync.aligned.m16n8k16.row.col.f32.f16.f16.f32 "
                 "{%0,%1,%2,%3}, {%4,%5,%6,%7}, {%8,%9}, {%0,%1,%2,%3};"
                 : "+f"(d[0]), "+f"(d[1]), "+f"(d[2]), "+f"(d[3])
                 : "r"(a0), "r"(a1), "r"(a2), "r"(a3), "r"(b0), "r"(b1));
}
#define CP_ASYNC16(saddr, gptr) \
    asm volatile("cp.async.cg.shared.global [%0], [%1], 16;" :: "r"(saddr), "l"(gptr))
#define CP_COMMIT() asm volatile("cp.async.commit_group;" ::: "memory")
#define CP_WAIT1()  asm volatile("cp.async.wait_group 1;" ::: "memory")
#define CP_WAIT0()  asm volatile("cp.async.wait_group 0;" ::: "memory")

// SW128 swizzle: rows of 128B, chunk16B index ^= (row & 7)
#define SWZ128(bo) ((bo) ^ (((bo) >> 3) & 0x70))

// ---------------------------------------------------------------------------
// X -> X_hi (fp16). Also zeroes g_m.
// ---------------------------------------------------------------------------
__global__ __launch_bounds__(256) void conv_x(const float* __restrict__ X)
{
    if (blockIdx.x < 512) g_m[blockIdx.x * 256 + threadIdx.x] = 0.0f;

    int t = blockIdx.x * 256 + threadIdx.x;
    int idx = t * 4;
    float4 v = *(const float4*)(X + idx);
    __half* base = g_abar + idx;
    *(__half2*)(base)     = __half2(__float2half(v.x), __float2half(v.y));
    *(__half2*)(base + 2) = __half2(__float2half(v.z), __float2half(v.w));
}

// W -> W_hi (fp16), 3 slabs
__global__ __launch_bounds__(256) void conv_w(const float* __restrict__ Wq,
                                              const float* __restrict__ Wk,
                                              const float* __restrict__ Wv)
{
    int which = blockIdx.y;
    const float* __restrict__ W = (which == 0) ? Wq : (which == 1) ? Wk : Wv;
    int t = blockIdx.x * 256 + threadIdx.x;
    int idx = t * 4;
    float4 v = *(const float4*)(W + idx);
    __half* base = g_bbar + (size_t)which * DMODEL * KEFF + idx;
    *(__half2*)(base)     = __half2(__float2half(v.x), __float2half(v.y));
    *(__half2*)(base + 2) = __half2(__float2half(v.z), __float2half(v.w));
}

// ---------------------------------------------------------------------------
// mma.sync fp16 projection (hi*hi, K=1024, NIT=16).
// slab 0 -> g_qs (+bq); slab 1 -> g_kh (mask,+bk); slab 2 -> g_vh (+bv)
// All outputs fp16 in [h][row][64] layout.
// CTA 128x128, BK=64, 8 warps (2x4), warp tile 64x32, 2-stage cp.async,
// 2 CTAs/SM. dynamic smem = 64KB
// ---------------------------------------------------------------------------
#define BKC 64
#define NITER (KEFF / BKC)   // 16
#define CHUNK_BYTES 16384    // 128 rows * 128B
#define BUF_BYTES   32768    // A chunk + B chunk

__global__ __launch_bounds__(256, 2)
void qkv_mma(int zbase,
             const float* __restrict__ amask,
             const float* __restrict__ bq,
             const float* __restrict__ bk,
             const float* __restrict__ bv)
{
    extern __shared__ __align__(1024) uint8_t smem[];
    __shared__ float sBias[128];

    const int tid  = threadIdx.x;
    const int wid  = tid >> 5;
    const int lane = tid & 31;
    const int which = blockIdx.z + zbase;
    const int m0 = blockIdx.y * 128;
    const int n0 = blockIdx.x * 128;

    const float* __restrict__ bias = (which == 0) ? bq : (which == 1) ? bk : bv;
    __half* __restrict__ Yh = (which == 0) ? g_qs : (which == 1) ? g_kh : g_vh;

    const __half* __restrict__ Ag = g_abar;
    const __half* __restrict__ Bg = g_bbar + (size_t)which * DMODEL * KEFF;

    const uint32_t sbase = smem_to_u32(smem);

    if (tid < 128) sBias[tid] = bias[n0 + tid];

    const int srow = tid >> 3;        // 0..31
    const int sc   = tid & 7;         // 16B chunk within 128B row

    auto stage = [&](int buf, int it) {
        const int ke = it * BKC;
        const uint32_t abase = sbase + buf * BUF_BYTES;
        const uint32_t bbase = abase + CHUNK_BYTES;
#pragma unroll
        for (int p = 0; p < 4; p++) {
            const int row = srow + p * 32;
            const uint32_t so = SWZ128((uint32_t)(row * 128 + sc * 16));
            CP_ASYNC16(abase + so, Ag + (size_t)(m0 + row) * KEFF + ke + sc * 8);
            CP_ASYNC16(bbase + so, Bg + (size_t)(n0 + row) * KEFF + ke + sc * 8);
        }
    };

    // warp tiling: 2 warps along M, 4 along N
    const int wm0 = (wid & 1) * 64;
    const int wn0 = (wid >> 1) * 32;

    float acc[16][4];
#pragma unroll
    for (int i = 0; i < 16; i++)
#pragma unroll
        for (int j = 0; j < 4; j++) acc[i][j] = 0.0f;

    const int a_row = wm0 + (lane & 15);
    const int a_ch  = (lane >> 4);
    const int b_g   = lane >> 3;
    const int b_row = wn0 + ((b_g >> 1) << 3) + (lane & 7);
    const int b_ch  = (b_g & 1);

    stage(0, 0);
    CP_COMMIT();

    for (int it = 0; it < NITER; it++) {
        if (it + 1 < NITER) {
            stage((it + 1) & 1, it + 1);
            CP_COMMIT();
            CP_WAIT1();
        } else {
            CP_WAIT0();
        }
        __syncthreads();

        const uint32_t abase = sbase + (it & 1) * BUF_BYTES;
        const uint32_t bbase = abase + CHUNK_BYTES;

#pragma unroll
        for (int ks = 0; ks < 4; ks++) {
            uint32_t a[4][4];
#pragma unroll
            for (int mi = 0; mi < 4; mi++) {
                const int row = a_row + mi * 16;
                const int ch  = ks * 2 + a_ch;
                ldsm_x4(a[mi][0], a[mi][1], a[mi][2], a[mi][3],
                        abase + SWZ128((uint32_t)(row * 128 + ch * 16)));
            }
            uint32_t b[2][4];
#pragma unroll
            for (int np = 0; np < 2; np++) {
                const int row = b_row + np * 16;
                const int ch  = ks * 2 + b_ch;
                ldsm_x4(b[np][0], b[np][1], b[np][2], b[np][3],
                        bbase + SWZ128((uint32_t)(row * 128 + ch * 16)));
            }
#pragma unroll
            for (int mi = 0; mi < 4; mi++)
#pragma unroll
                for (int ni = 0; ni < 4; ni++) {
                    const int np = ni >> 1, hf = (ni & 1) * 2;
                    mma_f16(acc[mi * 4 + ni], a[mi][0], a[mi][1], a[mi][2], a[mi][3],
                            b[np][hf], b[np][hf + 1]);
                }
        }
        __syncthreads();
    }

    // Epilogue: fp16 to [h][row][64] (mask for K)
    const int erow = wm0 + (lane >> 2);
    const int ecol = wn0 + (lane & 3) * 2;
#pragma unroll
    for (int mi = 0; mi < 4; mi++) {
        const int r0 = m0 + erow + mi * 16;
        const int r1 = r0 + 8;
        float mv0 = 1.0f, mv1 = 1.0f;
        if (which == 1) {
            mv0 = (amask[r0] >= 0.0f) ? 1.0f : 0.0f;
            mv1 = (amask[r1] >= 0.0f) ? 1.0f : 0.0f;
        }
#pragma unroll
        for (int ni = 0; ni < 4; ni++) {
            const int c = ecol + ni * 8;
            float v00 = (acc[mi * 4 + ni][0] + sBias[c + 0]) * mv0;
            float v01 = (acc[mi * 4 + ni][1] + sBias[c + 1]) * mv0;
            float v10 = (acc[mi * 4 + ni][2] + sBias[c + 0]) * mv1;
            float v11 = (acc[mi * 4 + ni][3] + sBias[c + 1]) * mv1;
            const int gcol = n0 + c;
            const int hh = gcol >> 6, d = gcol & 63;
            __half* p0 = Yh + ((size_t)hh * ROWS + r0) * 64 + d;
            __half* p1 = Yh + ((size_t)hh * ROWS + r1) * 64 + d;
            *(__half2*)p0 = __half2(__float2half(v00), __float2half(v01));
            *(__half2*)p1 = __half2(__float2half(v10), __float2half(v11));
        }
    }
}

// ---------------------------------------------------------------------------
// M[b,h] += K'[b,h]^T @ V[b,h] over a 64-key slice, tensor cores.
// A = K'^T (ldmatrix.trans), B = V (col-major via ldmatrix.trans).
// grid (32 bh, 32 splits), 128 threads (4 warps: M=64, N=16 each).
// ---------------------------------------------------------------------------
__global__ __launch_bounds__(128)
void kv_mma()
{
    __shared__ __align__(1024) uint8_t sK[8192];   // 64 keys x 64 halfs (128B rows)
    __shared__ __align__(1024) uint8_t sV[8192];

    const int tid  = threadIdx.x;
    const int wid  = tid >> 5;
    const int lane = tid & 31;
    const int bh = blockIdx.x;
    const int b = bh >> 4, h = bh & 15;
    const int kbase = blockIdx.y * 64;

    const uint32_t sKb = smem_to_u32(sK);
    const uint32_t sVb = smem_to_u32(sV);

    // load 64 keys x 128B per tile; thread t owns row t>>1, chunks (t&1)*4..+3
    {
        const int row = tid >> 1;
        const int c0  = (tid & 1) * 4;
        const size_t grow = ((size_t)h * ROWS + b * SEQ + kbase + row) * 64;
#pragma unroll
        for (int c = 0; c < 4; c++) {
            const uint32_t so = SWZ128((uint32_t)(row * 128 + (c0 + c) * 16));
            CP_ASYNC16(sKb + so, g_kh + grow + (c0 + c) * 8);
            CP_ASYNC16(sVb + so, g_vh + grow + (c0 + c) * 8);
        }
        CP_COMMIT();
    }
    CP_WAIT0();
    __syncthreads();

    const int wn0 = wid * 16;

    float acc[4][2][4];
#pragma unroll
    for (int i = 0; i < 4; i++)
#pragma unroll
        for (int j = 0; j < 2; j++)
#pragma unroll
            for (int k = 0; k < 4; k++) acc[i][j][k] = 0.0f;

    // lane components for trans loads
    const int ka_key = (lane & 7) + ((lane >> 4) & 1) * 8;   // + kk*16
    const int ka_dim = ((lane >> 3) & 1) * 8;                // + mi*16
    const int kb_key = (lane & 7) + ((lane >> 3) & 1) * 8;   // + kk*16
    const int kb_dim = wn0 + ((lane >> 4) & 1) * 8;

#pragma unroll
    for (int kk = 0; kk < 4; kk++) {
        uint32_t a[4][4];
#pragma unroll
        for (int mi = 0; mi < 4; mi++) {
            const int key = kk * 16 + ka_key;
            const int dim = mi * 16 + ka_dim;
            ldsm_x4_t(a[mi][0], a[mi][1], a[mi][2], a[mi][3],
                      sKb + SWZ128((uint32_t)(key * 128 + dim * 2)));
        }
        uint32_t bb[4];
        {
            const int key = kk * 16 + kb_key;
            ldsm_x4_t(bb[0], bb[1], bb[2], bb[3],
                      sVb + SWZ128((uint32_t)(key * 128 + kb_dim * 2)));
        }
#pragma unroll
        for (int mi = 0; mi < 4; mi++)
#pragma unroll
            for (int ni = 0; ni < 2; ni++)
                mma_f16(acc[mi][ni], a[mi][0], a[mi][1], a[mi][2], a[mi][3],
                        bb[ni * 2], bb[ni * 2 + 1]);
    }

    float* Mout = g_m + (size_t)bh * HDIM * HDIM;
    const int em = lane >> 2;
    const int en = (lane & 3) * 2;
#pragma unroll
    for (int mi = 0; mi < 4; mi++) {
        const int m = mi * 16 + em;
#pragma unroll
        for (int ni = 0; ni < 2; ni++) {
            const int n = wn0 + ni * 8 + en;
            atomicAdd(&Mout[m * HDIM + n],           acc[mi][ni][0]);
            atomicAdd(&Mout[m * HDIM + n + 1],       acc[mi][ni][1]);
            atomicAdd(&Mout[(m + 8) * HDIM + n],     acc[mi][ni][2]);
            atomicAdd(&Mout[(m + 8) * HDIM + n + 1], acc[mi][ni][3]);
        }
    }
}

// ---------------------------------------------------------------------------
// ctx = Q_hi @ M_hi via mma.sync fp16, K=64 (4 k16 steps).
// grid (16 stile, 16 h, 2 b), 256 threads, 8 warps (2M x 4N).
// dynamic smem: A 16KB @0, B 8KB @16384, Mfp32 16KB @24576 = 40KB
// ---------------------------------------------------------------------------
#define CTX_SMEM (16384 + 8192 + 16384)

__global__ __launch_bounds__(256)
void ctx_mma(float* __restrict__ out)
{
    extern __shared__ __align__(1024) uint8_t smem[];
    const uint32_t sbase = smem_to_u32(smem);
    const uint32_t sB = sbase + 16384;
    float* sM = (float*)(smem + 24576);

    const int tid  = threadIdx.x;
    const int wid  = tid >> 5;
    const int lane = tid & 31;
    const int st = blockIdx.x, h = blockIdx.y, b = blockIdx.z;
    const int s0 = st * 128;
    const size_t arow0 = (size_t)h * ROWS + b * SEQ + s0;

    // 1. stage A (Q_hi, 128 rows x 64 halfs = 128B/row) via cp.async
    {
        const int srow = tid >> 3;    // 0..31
        const int sc   = tid & 7;
#pragma unroll
        for (int p = 0; p < 4; p++) {
            const int row = srow + p * 32;
            CP_ASYNC16(sbase + SWZ128((uint32_t)(row * 128 + sc * 16)),
                       g_qs + (arow0 + row) * 64 + sc * 8);
        }
        CP_COMMIT();
    }

    // 2. load M (fp32 64x64) coalesced
    {
        const float* Msrc = g_m + (size_t)(b * NHEAD + h) * HDIM * HDIM;
#pragma unroll
        for (int i = 0; i < 4; i++) {
            int idx = tid * 16 + i * 4;
            *(float4*)(sM + idx) = *(const float4*)(Msrc + idx);
        }
    }
    __syncthreads();

    // 3. transpose-convert to fp16 B[j][k] = hi(M[k][j]), swizzled (128B rows)
    {
        const int j  = tid >> 2;
        const int k0 = (tid & 3) * 16;
#pragma unroll
        for (int i = 0; i < 16; i++) {
            const int k = k0 + i;
            const uint32_t bo = (uint32_t)(j * 128 + k * 2);
            *(__half*)(smem + 16384 + SWZ128(bo)) = __float2half(sM[k * 64 + j]);
        }
    }
    CP_WAIT0();
    __syncthreads();

    // 4. MMA: warp tile 64 M x 16 N, K = 64 (4 k16 steps)
    const int wm0 = (wid & 1) * 64;
    const int wn0 = (wid >> 1) * 16;

    float acc[8][4];
#pragma unroll
    for (int i = 0; i < 8; i++)
#pragma unroll
        for (int j = 0; j < 4; j++) acc[i][j] = 0.0f;

    const int a_row = wm0 + (lane & 15);
    const int a_ch  = (lane >> 4);
    const int b_g   = lane >> 3;
    const int b_row = wn0 + ((b_g >> 1) << 3) + (lane & 7);
    const int b_ch  = (b_g & 1);

#pragma unroll
    for (int ks = 0; ks < 4; ks++) {
        const int ch_a = ks * 2 + a_ch;
        const int ch_b = ks * 2 + b_ch;
        uint32_t a[4][4];
#pragma unroll
        for (int mi = 0; mi < 4; mi++)
            ldsm_x4(a[mi][0], a[mi][1], a[mi][2], a[mi][3],
                    sbase + SWZ128((uint32_t)((a_row + mi * 16) * 128 + ch_a * 16)));
        uint32_t bb[4];
        ldsm_x4(bb[0], bb[1], bb[2], bb[3],
                sB + SWZ128((uint32_t)(b_row * 128 + ch_b * 16)));
#pragma unroll
        for (int mi = 0; mi < 4; mi++)
#pragma unroll
            for (int ni = 0; ni < 2; ni++)
                mma_f16(acc[mi * 2 + ni], a[mi][0], a[mi][1], a[mi][2], a[mi][3],
                        bb[ni * 2], bb[ni * 2 + 1]);
    }

    // 5. epilogue
    const int erow = wm0 + (lane >> 2);
    const int ecol = wn0 + (lane & 3) * 2;
#pragma unroll
    for (int mi = 0; mi < 4; mi++) {
        const int r0 = s0 + erow + mi * 16;
        const int r1 = r0 + 8;
#pragma unroll
        for (int ni = 0; ni < 2; ni++) {
            const int c = h * HDIM + ecol + ni * 8;
            float* p0 = out + (size_t)(b * SEQ + r0) * DMODEL + c;
            float* p1 = out + (size_t)(b * SEQ + r1) * DMODEL + c;
            *(float2*)p0 = make_float2(acc[mi * 2 + ni][0], acc[mi * 2 + ni][1]);
            *(float2*)p1 = make_float2(acc[mi * 2 + ni][2], acc[mi * 2 + ni][3]);
        }
    }
}

// ---------------------------------------------------------------------------
// Launch: two-branch graph; join at ctx_mma.
// ---------------------------------------------------------------------------
extern "C" void kernel_launch(void* const* d_in, const int* in_sizes, int n_in,
                              void* d_out, int out_size)
{
    const float* X     = (const float*)d_in[0];
    const float* amask = (const float*)d_in[1];
    const float* Wq    = (const float*)d_in[2];
    const float* bq    = (const float*)d_in[3];
    const float* Wk    = (const float*)d_in[4];
    const float* bk    = (const float*)d_in[5];
    const float* Wv    = (const float*)d_in[6];
    const float* bv    = (const float*)d_in[7];
    float* out = (float*)d_out;

    static cudaStream_t s_kv = nullptr, s_q = nullptr;
    static cudaEvent_t ev_fork = nullptr, ev_convx = nullptr, ev_convw = nullptr,
                       ev_kv = nullptr, ev_q = nullptr;
    if (s_kv == nullptr) {
        cudaStreamCreateWithFlags(&s_kv, cudaStreamNonBlocking);
        cudaStreamCreateWithFlags(&s_q,  cudaStreamNonBlocking);
        cudaEventCreateWithFlags(&ev_fork,  cudaEventDisableTiming);
        cudaEventCreateWithFlags(&ev_convx, cudaEventDisableTiming);
        cudaEventCreateWithFlags(&ev_convw, cudaEventDisableTiming);
        cudaEventCreateWithFlags(&ev_kv,    cudaEventDisableTiming);
        cudaEventCreateWithFlags(&ev_q,     cudaEventDisableTiming);
        cudaFuncSetAttribute(qkv_mma, cudaFuncAttributeMaxDynamicSharedMemorySize,
                             2 * BUF_BYTES);
        cudaFuncSetAttribute(ctx_mma, cudaFuncAttributeMaxDynamicSharedMemorySize,
                             CTX_SMEM);
    }

    // fork both worker streams off the capture (default) stream
    cudaEventRecord(ev_fork, 0);
    cudaStreamWaitEvent(s_kv, ev_fork, 0);
    cudaStreamWaitEvent(s_q,  ev_fork, 0);

    // branch heads (independent)
    conv_x<<<ELEMS / 4 / 256, 256, 0, s_kv>>>(X);                       // X_hi + zero_m
    cudaEventRecord(ev_convx, s_kv);
    conv_w<<<dim3(DMODEL * DMODEL / 4 / 256, 3), 256, 0, s_q>>>(Wq, Wk, Wv);
    cudaEventRecord(ev_convw, s_q);

    // KV branch
    cudaStreamWaitEvent(s_kv, ev_convw, 0);
    qkv_mma<<<dim3(8, 32, 2), 256, 2 * BUF_BYTES, s_kv>>>(1, amask, bq, bk, bv); // K,V
    kv_mma<<<dim3(BATCH * NHEAD, 32), 128, 0, s_kv>>>();
    cudaEventRecord(ev_kv, s_kv);

    // Q branch
    cudaStreamWaitEvent(s_q, ev_convx, 0);
    qkv_mma<<<dim3(8, 32, 1), 256, 2 * BUF_BYTES, s_q>>>(0, amask, bq, bk, bv);  // Q
    cudaEventRecord(ev_q, s_q);

    // join on capture stream, final kernel
    cudaStreamWaitEvent(0, ev_kv, 0);
    cudaStreamWaitEvent(0, ev_q, 0);
    ctx_mma<<<dim3(SEQ / 128, NHEAD, BATCH), 256, CTX_SMEM>>>(out);
}